// round 1
// baseline (speedup 1.0000x reference)
#include <cuda_runtime.h>
#include <math.h>

namespace {

constexpr int V  = 3;
constexpr int C  = 32;
constexpr int CD = 8;
constexpr int D  = 32;
constexpr int H  = 128;
constexpr int W  = 160;
constexpr int HW = H * W;
constexpr float LAMB = 1.5f;

// Combined per-view projection: rot (3x3 row-major) at [0..8], translation at [9..11].
__device__ float g_M[V][12];
// Cost volume scratch (D, H, W)
__device__ float g_cost[D * HW];

// ---------------------------------------------------------------------------
// Kernel 0: P_v @ inv(P_ref), single thread, double precision Gauss-Jordan.
// ---------------------------------------------------------------------------
__global__ void setup_proj_kernel(const float* __restrict__ proj) {
    double a[4][4], inv[4][4];
    for (int i = 0; i < 4; i++)
        for (int j = 0; j < 4; j++) {
            a[i][j] = (double)proj[i * 4 + j];
            inv[i][j] = (i == j) ? 1.0 : 0.0;
        }
    for (int col = 0; col < 4; col++) {
        int piv = col;
        double best = fabs(a[col][col]);
        for (int r = col + 1; r < 4; r++) {
            double t = fabs(a[r][col]);
            if (t > best) { best = t; piv = r; }
        }
        if (piv != col) {
            for (int j = 0; j < 4; j++) {
                double t = a[col][j]; a[col][j] = a[piv][j]; a[piv][j] = t;
                t = inv[col][j]; inv[col][j] = inv[piv][j]; inv[piv][j] = t;
            }
        }
        double p = a[col][col];
        for (int j = 0; j < 4; j++) { a[col][j] /= p; inv[col][j] /= p; }
        for (int r = 0; r < 4; r++) {
            if (r == col) continue;
            double f = a[r][col];
            for (int j = 0; j < 4; j++) {
                a[r][j] -= f * a[col][j];
                inv[r][j] -= f * inv[col][j];
            }
        }
    }
    for (int v = 0; v < V; v++) {
        for (int r = 0; r < 3; r++) {
            for (int c2 = 0; c2 < 4; c2++) {
                double s = 0.0;
                for (int k = 0; k < 4; k++)
                    s += (double)proj[v * 16 + r * 4 + k] * inv[k][c2];
                if (c2 < 3) g_M[v][r * 3 + c2] = (float)s;
                else        g_M[v][9 + r]     = (float)s;
            }
        }
    }
}

// ---------------------------------------------------------------------------
// Kernel 1: cost volume. One thread per (depth, pixel); x is the fastest dim
// so ref loads are fully coalesced and warped gathers are nearly coalesced.
// ---------------------------------------------------------------------------
__global__ void __launch_bounds__(256) cost_kernel(
    const float* __restrict__ feat,    // (V, C, H, W)
    const float* __restrict__ deps,    // (V, CD, H, W)
    const float* __restrict__ dvals,   // (D, H, W)
    const float* __restrict__ regw)    // (40)
{
    const int idx = blockIdx.x * 256 + threadIdx.x;   // 0 .. D*HW-1
    const int d   = idx / HW;
    const int pix = idx - d * HW;
    const int y   = pix / W;
    const int x   = pix - y * W;
    const float xf = (float)x, yf = (float)y;
    const float dv = dvals[idx];

    int   lin[2][4];
    float wt[2][4];
#pragma unroll
    for (int v = 0; v < 2; v++) {
        const float* M = g_M[v + 1];
        float r0 = M[0] * xf + M[1] * yf + M[2];
        float r1 = M[3] * xf + M[4] * yf + M[5];
        float r2 = M[6] * xf + M[7] * yf + M[8];
        float zx = r0 * dv + M[9];
        float zy = r1 * dv + M[10];
        float zz = r2 * dv + M[11];
        float iz = 1.0f / zz;
        float px = zx * iz;
        float py = zy * iz;
        float x0f = floorf(px), y0f = floorf(py);
        int   x0  = (int)x0f,   y0  = (int)y0f;
        float wx = px - x0f, wy = py - y0f;
        float vx0 = (x0 >= 0  && x0 < W)      ? 1.0f : 0.0f;
        float vx1 = (x0 + 1 >= 0 && x0 + 1 < W) ? 1.0f : 0.0f;
        float vy0 = (y0 >= 0  && y0 < H)      ? 1.0f : 0.0f;
        float vy1 = (y0 + 1 >= 0 && y0 + 1 < H) ? 1.0f : 0.0f;
        wt[v][0] = (1.0f - wx) * (1.0f - wy) * vx0 * vy0;
        wt[v][1] = wx * (1.0f - wy) * vx1 * vy0;
        wt[v][2] = (1.0f - wx) * wy * vx0 * vy1;
        wt[v][3] = wx * wy * vx1 * vy1;
        int cx0 = min(max(x0, 0), W - 1);
        int cx1 = min(max(x0 + 1, 0), W - 1);
        int cy0 = min(max(y0, 0), H - 1);
        int cy1 = min(max(y0 + 1, 0), H - 1);
        lin[v][0] = cy0 * W + cx0;
        lin[v][1] = cy0 * W + cx1;
        lin[v][2] = cy1 * W + cx0;
        lin[v][3] = cy1 * W + cx1;
    }

    constexpr float inv3 = 1.0f / 3.0f;
    float cost = 0.0f;

#pragma unroll 8
    for (int c = 0; c < C; c++) {
        float rv = feat[c * HW + pix];
        const float* p1 = feat + (C + c) * HW;
        float s1 = p1[lin[0][0]] * wt[0][0] + p1[lin[0][1]] * wt[0][1]
                 + p1[lin[0][2]] * wt[0][2] + p1[lin[0][3]] * wt[0][3];
        const float* p2 = feat + (2 * C + c) * HW;
        float s2 = p2[lin[1][0]] * wt[1][0] + p2[lin[1][1]] * wt[1][1]
                 + p2[lin[1][2]] * wt[1][2] + p2[lin[1][3]] * wt[1][3];
        float s  = rv + s1 + s2;
        float sq = rv * rv + s1 * s1 + s2 * s2;
        float sm = s * inv3;
        cost += regw[c] * (sq * inv3 - sm * sm);
    }
#pragma unroll
    for (int c = 0; c < CD; c++) {
        float rv = deps[c * HW + pix];
        const float* p1 = deps + (CD + c) * HW;
        float s1 = p1[lin[0][0]] * wt[0][0] + p1[lin[0][1]] * wt[0][1]
                 + p1[lin[0][2]] * wt[0][2] + p1[lin[0][3]] * wt[0][3];
        const float* p2 = deps + (2 * CD + c) * HW;
        float s2 = p2[lin[1][0]] * wt[1][0] + p2[lin[1][1]] * wt[1][1]
                 + p2[lin[1][2]] * wt[1][2] + p2[lin[1][3]] * wt[1][3];
        float s  = rv + s1 + s2;
        float sq = rv * rv + s1 * s1 + s2 * s2;
        float sm = s * inv3;
        cost += regw[C + c] * (sq * inv3 - sm * sm);
    }

    g_cost[idx] = cost;
}

// ---------------------------------------------------------------------------
// Kernel 2: softmax over depth + depth / expected-variance moments.
// One thread per pixel, D=32 held fully in registers.
// ---------------------------------------------------------------------------
__global__ void __launch_bounds__(256) softmax_kernel(
    const float* __restrict__ dvals,   // (D, H, W)
    float* __restrict__ out)           // [depth HW | exp_var HW | prob D*HW]
{
    const int pix = blockIdx.x * 256 + threadIdx.x;
    if (pix >= HW) return;

    float cv[D];
#pragma unroll
    for (int d = 0; d < D; d++) cv[d] = g_cost[d * HW + pix];

    float m = cv[0];
#pragma unroll
    for (int d = 1; d < D; d++) m = fmaxf(m, cv[d]);

    float ssum = 0.0f;
#pragma unroll
    for (int d = 0; d < D; d++) { cv[d] = expf(cv[d] - m); ssum += cv[d]; }
    const float isum = 1.0f / ssum;

    float depthv = 0.0f;
#pragma unroll
    for (int d = 0; d < D; d++) {
        cv[d] *= isum;
        depthv += cv[d] * dvals[d * HW + pix];
    }

    float var = 0.0f;
#pragma unroll
    for (int d = 0; d < D; d++) {
        float t = dvals[d * HW + pix] - depthv;
        var += cv[d] * t * t;
        out[2 * HW + d * HW + pix] = cv[d];
    }

    out[pix]      = depthv;
    out[HW + pix] = LAMB * sqrtf(var);
}

} // namespace

extern "C" void kernel_launch(void* const* d_in, const int* in_sizes, int n_in,
                              void* d_out, int out_size) {
    // Assign inputs defensively by element count (all distinct):
    // features 1966080, deps 491520, proj 48, depth_values 655360, reg_w 40.
    const float* feat  = nullptr;
    const float* deps  = nullptr;
    const float* proj  = nullptr;
    const float* dvals = nullptr;
    const float* regw  = nullptr;
    for (int i = 0; i < n_in; i++) {
        switch (in_sizes[i]) {
            case V * C * HW:  feat  = (const float*)d_in[i]; break;
            case V * CD * HW: deps  = (const float*)d_in[i]; break;
            case V * 16:      proj  = (const float*)d_in[i]; break;
            case D * HW:      dvals = (const float*)d_in[i]; break;
            case C + CD:      regw  = (const float*)d_in[i]; break;
            default: break;
        }
    }
    float* out = (float*)d_out;

    setup_proj_kernel<<<1, 1>>>(proj);
    cost_kernel<<<(D * HW) / 256, 256>>>(feat, deps, dvals, regw);
    softmax_kernel<<<(HW + 255) / 256, 256>>>(dvals, out);
}

// round 2
// speedup vs baseline: 1.4484x; 1.4484x over previous
#include <cuda_runtime.h>
#include <math.h>

namespace {

constexpr int V  = 3;
constexpr int C  = 32;
constexpr int CD = 8;
constexpr int D  = 32;
constexpr int H  = 128;
constexpr int W  = 160;
constexpr int HW = H * W;
constexpr float LAMB = 1.5f;

// Cost volume scratch (D, H, W)
__device__ float g_cost[D * HW];

// ---------------------------------------------------------------------------
// fp32 closed-form 4x4 inverse (adjugate). Matches reference's fp32
// jnp.linalg.inv within tolerance; input matrix is well-conditioned (K @ Rt).
// ---------------------------------------------------------------------------
__device__ __forceinline__ void inv4x4(const float* m, float* inv) {
    inv[0]  =  m[5]*m[10]*m[15] - m[5]*m[11]*m[14] - m[9]*m[6]*m[15]
             + m[9]*m[7]*m[14] + m[13]*m[6]*m[11] - m[13]*m[7]*m[10];
    inv[4]  = -m[4]*m[10]*m[15] + m[4]*m[11]*m[14] + m[8]*m[6]*m[15]
             - m[8]*m[7]*m[14] - m[12]*m[6]*m[11] + m[12]*m[7]*m[10];
    inv[8]  =  m[4]*m[9]*m[15] - m[4]*m[11]*m[13] - m[8]*m[5]*m[15]
             + m[8]*m[7]*m[13] + m[12]*m[5]*m[11] - m[12]*m[7]*m[9];
    inv[12] = -m[4]*m[9]*m[14] + m[4]*m[10]*m[13] + m[8]*m[5]*m[14]
             - m[8]*m[6]*m[13] - m[12]*m[5]*m[10] + m[12]*m[6]*m[9];
    inv[1]  = -m[1]*m[10]*m[15] + m[1]*m[11]*m[14] + m[9]*m[2]*m[15]
             - m[9]*m[3]*m[14] - m[13]*m[2]*m[11] + m[13]*m[3]*m[10];
    inv[5]  =  m[0]*m[10]*m[15] - m[0]*m[11]*m[14] - m[8]*m[2]*m[15]
             + m[8]*m[3]*m[14] + m[12]*m[2]*m[11] - m[12]*m[3]*m[10];
    inv[9]  = -m[0]*m[9]*m[15] + m[0]*m[11]*m[13] + m[8]*m[1]*m[15]
             - m[8]*m[3]*m[13] - m[12]*m[1]*m[11] + m[12]*m[3]*m[9];
    inv[13] =  m[0]*m[9]*m[14] - m[0]*m[10]*m[13] - m[8]*m[1]*m[14]
             + m[8]*m[2]*m[13] + m[12]*m[1]*m[10] - m[12]*m[2]*m[9];
    inv[2]  =  m[1]*m[6]*m[15] - m[1]*m[7]*m[14] - m[5]*m[2]*m[15]
             + m[5]*m[3]*m[14] + m[13]*m[2]*m[7] - m[13]*m[3]*m[6];
    inv[6]  = -m[0]*m[6]*m[15] + m[0]*m[7]*m[14] + m[4]*m[2]*m[15]
             - m[4]*m[3]*m[14] - m[12]*m[2]*m[7] + m[12]*m[3]*m[6];
    inv[10] =  m[0]*m[5]*m[15] - m[0]*m[7]*m[13] - m[4]*m[1]*m[15]
             + m[4]*m[3]*m[13] + m[12]*m[1]*m[7] - m[12]*m[3]*m[5];
    inv[14] = -m[0]*m[5]*m[14] + m[0]*m[6]*m[13] + m[4]*m[1]*m[14]
             - m[4]*m[2]*m[13] - m[12]*m[1]*m[6] + m[12]*m[2]*m[5];
    inv[3]  = -m[1]*m[6]*m[11] + m[1]*m[7]*m[10] + m[5]*m[2]*m[11]
             - m[5]*m[3]*m[10] - m[9]*m[2]*m[7] + m[9]*m[3]*m[6];
    inv[7]  =  m[0]*m[6]*m[11] - m[0]*m[7]*m[10] - m[4]*m[2]*m[11]
             + m[4]*m[3]*m[10] + m[8]*m[2]*m[7] - m[8]*m[3]*m[6];
    inv[11] = -m[0]*m[5]*m[11] + m[0]*m[7]*m[9] + m[4]*m[1]*m[11]
             - m[4]*m[3]*m[9] - m[8]*m[1]*m[7] + m[8]*m[3]*m[5];
    inv[15] =  m[0]*m[5]*m[10] - m[0]*m[6]*m[9] - m[4]*m[1]*m[10]
             + m[4]*m[2]*m[9] + m[8]*m[1]*m[6] - m[8]*m[2]*m[5];
    float det = m[0]*inv[0] + m[1]*inv[4] + m[2]*inv[8] + m[3]*inv[12];
    float id = 1.0f / det;
    for (int i = 0; i < 16; i++) inv[i] *= id;
}

// ---------------------------------------------------------------------------
// Kernel 1: cost volume. One thread per (depth, pixel); x is the fastest dim
// so ref loads are fully coalesced and warped gathers are nearly coalesced.
// Thread 0 of each block computes the combined projections (src views 1,2)
// into shared memory; ~800 cycles, hidden by concurrent blocks.
// ---------------------------------------------------------------------------
__global__ void __launch_bounds__(256) cost_kernel(
    const float* __restrict__ feat,    // (V, C, H, W)
    const float* __restrict__ deps,    // (V, CD, H, W)
    const float* __restrict__ dvals,   // (D, H, W)
    const float* __restrict__ regw,    // (40)
    const float* __restrict__ proj)    // (V, 4, 4)
{
    __shared__ float sM[2][12];        // rot[0..8], tr[9..11] per src view
    if (threadIdx.x == 0) {
        float inv[16];
        inv4x4(proj, inv);             // inverse of ref projection (view 0)
        for (int v = 1; v < V; v++) {
            const float* P = proj + v * 16;
            for (int r = 0; r < 3; r++) {
                for (int c2 = 0; c2 < 4; c2++) {
                    float s = P[r*4+0]*inv[0*4+c2] + P[r*4+1]*inv[1*4+c2]
                            + P[r*4+2]*inv[2*4+c2] + P[r*4+3]*inv[3*4+c2];
                    if (c2 < 3) sM[v-1][r*3 + c2] = s;
                    else        sM[v-1][9 + r]    = s;
                }
            }
        }
    }
    __syncthreads();

    const int idx = blockIdx.x * 256 + threadIdx.x;   // 0 .. D*HW-1
    const int d   = idx / HW;
    const int pix = idx - d * HW;
    const int y   = pix / W;
    const int x   = pix - y * W;
    const float xf = (float)x, yf = (float)y;
    const float dv = dvals[idx];

    int   lin[2][4];
    float wt[2][4];
#pragma unroll
    for (int v = 0; v < 2; v++) {
        const float* M = sM[v];
        float r0 = M[0] * xf + M[1] * yf + M[2];
        float r1 = M[3] * xf + M[4] * yf + M[5];
        float r2 = M[6] * xf + M[7] * yf + M[8];
        float zx = r0 * dv + M[9];
        float zy = r1 * dv + M[10];
        float zz = r2 * dv + M[11];
        float iz = 1.0f / zz;
        float px = zx * iz;
        float py = zy * iz;
        float x0f = floorf(px), y0f = floorf(py);
        int   x0  = (int)x0f,   y0  = (int)y0f;
        float wx = px - x0f, wy = py - y0f;
        float vx0 = (x0 >= 0  && x0 < W)        ? 1.0f : 0.0f;
        float vx1 = (x0 + 1 >= 0 && x0 + 1 < W) ? 1.0f : 0.0f;
        float vy0 = (y0 >= 0  && y0 < H)        ? 1.0f : 0.0f;
        float vy1 = (y0 + 1 >= 0 && y0 + 1 < H) ? 1.0f : 0.0f;
        wt[v][0] = (1.0f - wx) * (1.0f - wy) * vx0 * vy0;
        wt[v][1] = wx * (1.0f - wy) * vx1 * vy0;
        wt[v][2] = (1.0f - wx) * wy * vx0 * vy1;
        wt[v][3] = wx * wy * vx1 * vy1;
        int cx0 = min(max(x0, 0), W - 1);
        int cx1 = min(max(x0 + 1, 0), W - 1);
        int cy0 = min(max(y0, 0), H - 1);
        int cy1 = min(max(y0 + 1, 0), H - 1);
        lin[v][0] = cy0 * W + cx0;
        lin[v][1] = cy0 * W + cx1;
        lin[v][2] = cy1 * W + cx0;
        lin[v][3] = cy1 * W + cx1;
    }

    constexpr float inv3 = 1.0f / 3.0f;
    float cost = 0.0f;

#pragma unroll 8
    for (int c = 0; c < C; c++) {
        float rv = feat[c * HW + pix];
        const float* p1 = feat + (C + c) * HW;
        float s1 = p1[lin[0][0]] * wt[0][0] + p1[lin[0][1]] * wt[0][1]
                 + p1[lin[0][2]] * wt[0][2] + p1[lin[0][3]] * wt[0][3];
        const float* p2 = feat + (2 * C + c) * HW;
        float s2 = p2[lin[1][0]] * wt[1][0] + p2[lin[1][1]] * wt[1][1]
                 + p2[lin[1][2]] * wt[1][2] + p2[lin[1][3]] * wt[1][3];
        float s  = rv + s1 + s2;
        float sq = rv * rv + s1 * s1 + s2 * s2;
        float sm = s * inv3;
        cost += regw[c] * (sq * inv3 - sm * sm);
    }
#pragma unroll
    for (int c = 0; c < CD; c++) {
        float rv = deps[c * HW + pix];
        const float* p1 = deps + (CD + c) * HW;
        float s1 = p1[lin[0][0]] * wt[0][0] + p1[lin[0][1]] * wt[0][1]
                 + p1[lin[0][2]] * wt[0][2] + p1[lin[0][3]] * wt[0][3];
        const float* p2 = deps + (2 * CD + c) * HW;
        float s2 = p2[lin[1][0]] * wt[1][0] + p2[lin[1][1]] * wt[1][1]
                 + p2[lin[1][2]] * wt[1][2] + p2[lin[1][3]] * wt[1][3];
        float s  = rv + s1 + s2;
        float sq = rv * rv + s1 * s1 + s2 * s2;
        float sm = s * inv3;
        cost += regw[C + c] * (sq * inv3 - sm * sm);
    }

    g_cost[idx] = cost;
}

// ---------------------------------------------------------------------------
// Kernel 2: softmax over depth + depth / expected-variance moments.
// One thread per pixel, D=32 held fully in registers.
// ---------------------------------------------------------------------------
__global__ void __launch_bounds__(256) softmax_kernel(
    const float* __restrict__ dvals,   // (D, H, W)
    float* __restrict__ out)           // [depth HW | exp_var HW | prob D*HW]
{
    const int pix = blockIdx.x * 256 + threadIdx.x;
    if (pix >= HW) return;

    float cv[D];
#pragma unroll
    for (int d = 0; d < D; d++) cv[d] = g_cost[d * HW + pix];

    float m = cv[0];
#pragma unroll
    for (int d = 1; d < D; d++) m = fmaxf(m, cv[d]);

    float ssum = 0.0f;
#pragma unroll
    for (int d = 0; d < D; d++) { cv[d] = expf(cv[d] - m); ssum += cv[d]; }
    const float isum = 1.0f / ssum;

    float depthv = 0.0f;
#pragma unroll
    for (int d = 0; d < D; d++) {
        cv[d] *= isum;
        depthv += cv[d] * dvals[d * HW + pix];
    }

    float var = 0.0f;
#pragma unroll
    for (int d = 0; d < D; d++) {
        float t = dvals[d * HW + pix] - depthv;
        var += cv[d] * t * t;
        out[2 * HW + d * HW + pix] = cv[d];
    }

    out[pix]      = depthv;
    out[HW + pix] = LAMB * sqrtf(var);
}

} // namespace

extern "C" void kernel_launch(void* const* d_in, const int* in_sizes, int n_in,
                              void* d_out, int out_size) {
    // Assign inputs defensively by element count (all distinct):
    // features 1966080, deps 491520, proj 48, depth_values 655360, reg_w 40.
    const float* feat  = nullptr;
    const float* deps  = nullptr;
    const float* proj  = nullptr;
    const float* dvals = nullptr;
    const float* regw  = nullptr;
    for (int i = 0; i < n_in; i++) {
        switch (in_sizes[i]) {
            case V * C * HW:  feat  = (const float*)d_in[i]; break;
            case V * CD * HW: deps  = (const float*)d_in[i]; break;
            case V * 16:      proj  = (const float*)d_in[i]; break;
            case D * HW:      dvals = (const float*)d_in[i]; break;
            case C + CD:      regw  = (const float*)d_in[i]; break;
            default: break;
        }
    }
    float* out = (float*)d_out;

    cost_kernel<<<(D * HW) / 256, 256>>>(feat, deps, dvals, regw, proj);
    softmax_kernel<<<(HW + 255) / 256, 256>>>(dvals, out);
}